// round 16
// baseline (speedup 1.0000x reference)
#include <cuda_runtime.h>
#include <cuda_bf16.h>
#include <math.h>
#include <stdint.h>

#define Bb 8
#define Nn 1024
#define Dd 1024
#define Hh 16
#define DHh 64
#define Mrows (Bb*Nn)

// 0.125 (1/sqrt(DH)) * log2(e): folds attn scale + base-2 softmax into Q
#define SCQ 0.18033688011112042f

// ---- scratch (static device globals; no allocations allowed) ----
__device__ float g_mha[Mrows*Dd];                 // o @ Wo^T + bo (fp32)
__device__ __nv_bfloat16 g_sX3[3ull*Mrows*Dd];    // converted k,q,r
__device__ __nv_bfloat16 g_sW4[4ull*Dd*Dd];       // converted Wk,Wq,Wv,Wo
__device__ __nv_bfloat16 g_bQ[Bb*Hh*Nn*DHh];      // [b,h,n,dh] (pre-scaled by SCQ)
__device__ __nv_bfloat16 g_bK[Bb*Hh*Nn*DHh];
__device__ __nv_bfloat16 g_bV[Bb*Hh*Nn*DHh];
__device__ __nv_bfloat16 g_bO[Mrows*Dd];          // attention out, [B*N, D] flat bf16

// ============================================================
// helpers
// ============================================================
__device__ __forceinline__ uint32_t smem_u32(const void* p) {
    return (uint32_t)__cvta_generic_to_shared(p);
}

#define CPA(dst, src) asm volatile("cp.async.cg.shared.global [%0], [%1], 16;" :: "r"(dst), "l"(src))
#define CPC()  asm volatile("cp.async.commit_group;" ::: "memory")
#define CPW2() asm volatile("cp.async.wait_group 2;" ::: "memory")
#define CPW1() asm volatile("cp.async.wait_group 1;" ::: "memory")
#define CPW0() asm volatile("cp.async.wait_group 0;" ::: "memory")

#define LDSM4(r, a) \
    asm volatile("ldmatrix.sync.aligned.m8n8.x4.shared.b16 {%0,%1,%2,%3}, [%4];" \
        : "=r"((r)[0]), "=r"((r)[1]), "=r"((r)[2]), "=r"((r)[3]) : "r"(a))

#define LDSM4T(r, a) \
    asm volatile("ldmatrix.sync.aligned.m8n8.x4.trans.shared.b16 {%0,%1,%2,%3}, [%4];" \
        : "=r"((r)[0]), "=r"((r)[1]), "=r"((r)[2]), "=r"((r)[3]) : "r"(a))

#define MMA16816(c, a, b0, b1) \
    asm volatile("mma.sync.aligned.m16n8k16.row.col.f32.bf16.bf16.f32 " \
        "{%0,%1,%2,%3},{%4,%5,%6,%7},{%8,%9},{%0,%1,%2,%3};" \
        : "+f"((c)[0]), "+f"((c)[1]), "+f"((c)[2]), "+f"((c)[3]) \
        : "r"((a)[0]), "r"((a)[1]), "r"((a)[2]), "r"((a)[3]), "r"(b0), "r"(b1))

__device__ __forceinline__ uint32_t packbf(float hi, float lo) {
    uint32_t d;
    asm("cvt.rn.bf16x2.f32 %0, %1, %2;" : "=r"(d) : "f"(hi), "f"(lo));
    return d;
}

// fast 2^x, |x| bounded, cubic (P feeds bf16; poly err << bf16 rounding)
__device__ __forceinline__ float exp2q(float x) {
    float z = x + 12582912.0f;
    int   xi = __float_as_int(z) - 0x4B400000;
    float f = x - (z - 12582912.0f);
    float p = fmaf(f, 0.0790211f, 0.2243367f);
    p = fmaf(f, p, 0.6958793f);
    p = fmaf(f, p, 1.0f);
    return __int_as_float(__float_as_int(p) + (xi << 23));
}

// swizzled smem byte offset: 64B-row arrays (gemm)
__device__ __forceinline__ uint32_t swz(uint32_t r, uint32_t kb) {
    return r * 64u + (kb ^ (((r >> 1) & 3u) << 4));
}
// swizzled smem byte offset: 128B-row arrays (attn), u = 16B-unit index 0..7
__device__ __forceinline__ uint32_t offA(uint32_t r, uint32_t u) {
    return r * 128u + ((u ^ (r & 7u)) << 4);
}

// ============================================================
// fused fp32 -> bf16 converters (4 float4 per thread)
// ============================================================
__global__ __launch_bounds__(256) void convert_x3(const float* __restrict__ k,
                                                  const float* __restrict__ q,
                                                  const float* __restrict__ r)
{
    int which = blockIdx.y;
    const float* src = (which == 0) ? k : (which == 1) ? q : r;
    __nv_bfloat16* dst = g_sX3 + (size_t)which * (Mrows * Dd);
    int base = blockIdx.x * 1024 + threadIdx.x;
    #pragma unroll
    for (int u = 0; u < 4; u++) {
        int i = base + u * 256;
        float4 v = ((const float4*)src)[i];
        uint2 pk;
        pk.x = packbf(v.y, v.x);
        pk.y = packbf(v.w, v.z);
        ((uint2*)dst)[i] = pk;
    }
}

__global__ __launch_bounds__(256) void convert_w4(const float* __restrict__ w0,
                                                  const float* __restrict__ w1,
                                                  const float* __restrict__ w2,
                                                  const float* __restrict__ w3)
{
    int which = blockIdx.y;
    const float* src = (which == 0) ? w0 : (which == 1) ? w1
                     : (which == 2) ? w2 : w3;
    __nv_bfloat16* dst = g_sW4 + (size_t)which * (Dd * Dd);
    int base = blockIdx.x * 1024 + threadIdx.x;
    #pragma unroll
    for (int u = 0; u < 4; u++) {
        int i = base + u * 256;
        float4 v = ((const float4*)src)[i];
        uint2 pk;
        pk.x = packbf(v.y, v.x);
        pk.y = packbf(v.w, v.z);
        ((uint2*)dst)[i] = pk;
    }
}

// ============================================================
// bf16 mma GEMM core: out = X @ W^T + bias
// CTA 128x128, 4 warps (2x2), warp tile 64x64 (acc 128 regs),
// K-chunk 32, 4-stage cp.async ring (64KB), 2 CTAs/SM.
// ============================================================
#define GARR 8192                        // one 128-row x 64B array
#define GSTAGE (2*GARR)                  // A + B = 16KB
#define GEMM_SMEM (4*GSTAGE)             // 64KB

__device__ __forceinline__ void gemm_core(const __nv_bfloat16* __restrict__ A,
                                          const __nv_bfloat16* __restrict__ W,
                                          const float* __restrict__ bias,
                                          int out_sel, char* smem)
{
    uint32_t sb = smem_u32(smem);

    int t = threadIdx.x;                  // 0..127
    int wid = t >> 5, lane = t & 31;
    int wm = wid >> 1, wn = wid & 1;
    int m0 = blockIdx.y * 128, n0 = blockIdx.x * 128;

    // copy: thread t -> row t, all 4 16B units of A row + B row
    const char* pA = (const char*)(A + (size_t)(m0 + t) * 1024);
    const char* pB = (const char*)(W + (size_t)(n0 + t) * 1024);
    uint32_t dd[4];
    #pragma unroll
    for (int j = 0; j < 4; j++)
        dd[j] = swz((uint32_t)t, (uint32_t)(j * 16));

    auto issue = [&](int it) {
        uint32_t st = sb + (uint32_t)(it & 3) * GSTAGE;
        size_t kb = (size_t)it * 64;      // 32 bf16 per chunk
        #pragma unroll
        for (int j = 0; j < 4; j++) {
            CPA(st + dd[j], pA + kb + j * 16);
            CPA(st + GARR + dd[j], pB + kb + j * 16);
        }
        CPC();
    };

    float acc[4][8][4];
    #pragma unroll
    for (int i = 0; i < 4; i++)
        #pragma unroll
        for (int j = 0; j < 8; j++)
            #pragma unroll
            for (int u = 0; u < 4; u++) acc[i][j][u] = 0.f;

    // A fragment addrs: rows wm*64 + mt*16 + (lane&15), unit kk*2 + (lane>>4)
    uint32_t aAddr[4][2];
    #pragma unroll
    for (int mt = 0; mt < 4; mt++)
        #pragma unroll
        for (int kk = 0; kk < 2; kk++)
            aAddr[mt][kk] = swz((uint32_t)(wm*64 + mt*16 + (lane & 15)),
                                (uint32_t)(kk*32 + ((lane >> 4) << 4)));
    // B fragment addrs (16-row x4: gives both n8 frags of an n16 block per k16):
    // rows wn*64 + np*16 + (lane&15), unit kk*2 + (lane>>4)
    uint32_t bAddr[4][2];
    #pragma unroll
    for (int np = 0; np < 4; np++)
        #pragma unroll
        for (int kk = 0; kk < 2; kk++)
            bAddr[np][kk] = swz((uint32_t)(wn*64 + np*16 + (lane & 15)),
                                (uint32_t)(kk*32 + ((lane >> 4) << 4)));

    issue(0); issue(1); issue(2);

    for (int it = 0; it < 32; it++) {
        if (it < 30) CPW2(); else if (it == 30) CPW1(); else CPW0();
        __syncthreads();

        uint32_t st = sb + (uint32_t)(it & 3) * GSTAGE;

        uint32_t ah[4][2][4];
        #pragma unroll
        for (int mt = 0; mt < 4; mt++)
            #pragma unroll
            for (int kk = 0; kk < 2; kk++)
                LDSM4(ah[mt][kk], st + aAddr[mt][kk]);

        #pragma unroll
        for (int np = 0; np < 4; np++) {
            #pragma unroll
            for (int kk = 0; kk < 2; kk++) {
                uint32_t bf[4];
                LDSM4(bf, st + GARR + bAddr[np][kk]);
                // bf[0]=n8lo k0-7, bf[1]=n8hi k0-7, bf[2]=n8lo k8-15, bf[3]=n8hi k8-15
                #pragma unroll
                for (int mt = 0; mt < 4; mt++) {
                    MMA16816(acc[mt][2*np],     ah[mt][kk], bf[0], bf[2]);
                    MMA16816(acc[mt][2*np + 1], ah[mt][kk], bf[1], bf[3]);
                }
            }
        }

        if (it < 29) issue(it + 3);   // writes slot (it-1)&3: safe post-barrier
    }

    // ---- epilogue
    float sc = (out_sel == 1) ? SCQ : 1.0f;
    #pragma unroll
    for (int mt = 0; mt < 4; mt++) {
        #pragma unroll
        for (int nt = 0; nt < 8; nt++) {
            int row = m0 + wm*64 + mt*16 + (lane >> 2);
            int col = n0 + wn*64 + nt*8 + (lane & 3)*2;
            float b0v = bias[col], b1v = bias[col + 1];
            float v0 = (acc[mt][nt][0] + b0v) * sc;
            float v1 = (acc[mt][nt][1] + b1v) * sc;
            float v2 = (acc[mt][nt][2] + b0v) * sc;
            float v3 = (acc[mt][nt][3] + b1v) * sc;
            if (out_sel < 3) {
                __nv_bfloat16* out = (out_sel == 0) ? g_bK : (out_sel == 1) ? g_bQ : g_bV;
                int bidx = row >> 10;
                int iseq = row & 1023;
                int h = col >> 6;
                int dd2 = col & 63;
                size_t base = (((size_t)(bidx*Hh + h) * Nn) + iseq) * DHh + dd2;
                *(uint32_t*)(out + base)           = packbf(v1, v0);
                *(uint32_t*)(out + base + 8*DHh)   = packbf(v3, v2);
            } else {
                float* out = g_mha;
                *(float2*)(out + (size_t)row * Dd + col)       = make_float2(v0, v1);
                *(float2*)(out + (size_t)(row + 8) * Dd + col) = make_float2(v2, v3);
            }
        }
    }
}

__global__ __launch_bounds__(128, 2) void gemm_qkv(const float* __restrict__ bk,
                                                   const float* __restrict__ bq,
                                                   const float* __restrict__ bv)
{
    extern __shared__ __align__(16) char smem[];
    int z = blockIdx.z;
    const float* bias = (z == 0) ? bk : (z == 1) ? bq : bv;
    gemm_core(g_sX3 + (size_t)z * (Mrows * Dd),
              g_sW4 + (size_t)z * (Dd * Dd),
              bias, z, smem);
}

__global__ __launch_bounds__(128, 2) void gemm_o(const float* __restrict__ bo)
{
    extern __shared__ __align__(16) char smem[];
    gemm_core(g_bO, g_sW4 + 3ull * (Dd * Dd), bo, 3, smem);
}

// ============================================================
// Flash attention: 4 warps x 32 Q-rows (K/V frags reused 2x),
// one-pass softmax, row sums via ones-MMA, cubic exp2.
// ============================================================
#define AQ_BYTES 16384
#define AKV_BYTES 8192
#define ATTN_SMEM (AQ_BYTES + 6*AKV_BYTES)   // 64KB

__global__ __launch_bounds__(128, 2) void attn_mma()
{
    extern __shared__ __align__(16) char dsm[];
    uint32_t sQ = smem_u32(dsm);
    uint32_t sKb = sQ + AQ_BYTES;
    uint32_t sVb = sKb + 3 * AKV_BYTES;

    int t = threadIdx.x;                 // 0..127
    int w = t >> 5, lane = t & 31;
    int bh = blockIdx.y;
    int qb = blockIdx.x * 128;
    int b = bh >> 4, h = bh & 15;

    const __nv_bfloat16* Qg = g_bQ + ((size_t)bh * Nn + qb) * DHh;
    const __nv_bfloat16* Kg = g_bK + (size_t)bh * Nn * DHh;
    const __nv_bfloat16* Vg = g_bV + (size_t)bh * Nn * DHh;

    // stage Q (128 rows x 128B = 16KB, 128 threads x 8 uint4)
    #pragma unroll
    for (int i = 0; i < 8; i++) {
        int idx = t + i * 128;
        int r = idx >> 3, u = idx & 7;
        uint4 v = *(const uint4*)(Qg + r * DHh + u * 8);
        *(uint4*)(dsm + offA((uint32_t)r, (uint32_t)u)) = v;
    }

    uint32_t a0[4];
    #pragma unroll
    for (int i = 0; i < 4; i++)
        a0[i] = (uint32_t)(lane & 15) * 128u
              + ((((uint32_t)i * 2u + (uint32_t)(lane >> 4)) ^ (uint32_t)(lane & 7)) << 4);

    // K/V chunk loader: thread -> row t>>1, 4 units at (t&1)*4
    int cr = t >> 1;
    int cu4 = (t & 1) * 4;
    uint32_t ko[4];
    #pragma unroll
    for (int j = 0; j < 4; j++)
        ko[j] = offA((uint32_t)cr, (uint32_t)(cu4 + j));
    auto issue = [&](int c) {
        int st = c % 3;
        const __nv_bfloat16* ks = Kg + (size_t)(c * 64 + cr) * DHh + cu4 * 8;
        const __nv_bfloat16* vs = Vg + (size_t)(c * 64 + cr) * DHh + cu4 * 8;
        uint32_t kslot = sKb + (uint32_t)st * AKV_BYTES;
        uint32_t vslot = sVb + (uint32_t)st * AKV_BYTES;
        #pragma unroll
        for (int j = 0; j < 4; j++) {
            CPA(kslot + ko[j], ks + j * 8);
            CPA(vslot + ko[j], vs + j * 8);
        }
        CPC();
    };

    issue(0); issue(1);
    __syncthreads();

    // Q fragments: 2 m-tiles (rows w*32 .. +31)
    uint32_t aQ[2][4][4];
    #pragma unroll
    for (int mt = 0; mt < 2; mt++)
        #pragma unroll
        for (int ks = 0; ks < 4; ks++)
            LDSM4(aQ[mt][ks], sQ + (uint32_t)(w * 4096 + mt * 2048) + a0[ks]);

    float oacc[2][8][4];
    #pragma unroll
    for (int mt = 0; mt < 2; mt++)
        #pragma unroll
        for (int nt = 0; nt < 8; nt++)
            #pragma unroll
            for (int u = 0; u < 4; u++) oacc[mt][nt][u] = 0.f;
    float lacc[2][4];
    #pragma unroll
    for (int mt = 0; mt < 2; mt++)
        #pragma unroll
        for (int u = 0; u < 4; u++) lacc[mt][u] = 0.f;
    const uint32_t ONES = 0x3F803F80u;

    for (int c = 0; c < 16; c++) {
        if (c < 15) CPW1(); else CPW0();
        __syncthreads();
        int st = c % 3;
        uint32_t kslot = sKb + (uint32_t)st * AKV_BYTES;
        uint32_t vslot = sVb + (uint32_t)st * AKV_BYTES;

        // ---- S = Q @ K^T (32 x 64 per warp); K frags shared by both m-tiles
        float s[2][8][4];
        #pragma unroll
        for (int mt = 0; mt < 2; mt++)
            #pragma unroll
            for (int nt = 0; nt < 8; nt++)
                #pragma unroll
                for (int u = 0; u < 4; u++) s[mt][nt][u] = 0.f;

        #pragma unroll
        for (int sg = 0; sg < 4; sg++) {
            uint32_t sgo = kslot + (uint32_t)(sg * 2048);
            uint32_t kf[4][4];
            #pragma unroll
            for (int ks = 0; ks < 4; ks++)
                LDSM4(kf[ks], sgo + a0[ks]);
            #pragma unroll
            for (int ks = 0; ks < 4; ks++)
                #pragma unroll
                for (int mt = 0; mt < 2; mt++) {
                    MMA16816(s[mt][2*sg],     aQ[mt][ks], kf[ks][0], kf[ks][2]);
                    MMA16816(s[mt][2*sg + 1], aQ[mt][ks], kf[ks][1], kf[ks][3]);
                }
        }

        // ---- p = 2^s, pack
        uint32_t aP[2][4][4];
        #pragma unroll
        for (int mt = 0; mt < 2; mt++) {
            #pragma unroll
            for (int nt = 0; nt < 8; nt++) {
                s[mt][nt][0] = exp2q(s[mt][nt][0]);
                s[mt][nt][1] = exp2q(s[mt][nt][1]);
                s[mt][nt][2] = exp2q(s[mt][nt][2]);
                s[mt][nt][3] = exp2q(s[mt][nt][3]);
            }
            #pragma unroll
            for (int ks = 0; ks < 4; ks++) {
                aP[mt][ks][0] = packbf(s[mt][2*ks][1],   s[mt][2*ks][0]);
                aP[mt][ks][1] = packbf(s[mt][2*ks][3],   s[mt][2*ks][2]);
                aP[mt][ks][2] = packbf(s[mt][2*ks+1][1], s[mt][2*ks+1][0]);
                aP[mt][ks][3] = packbf(s[mt][2*ks+1][3], s[mt][2*ks+1][2]);
            }
        }

        // ---- row sums on tensor pipe
        #pragma unroll
        for (int mt = 0; mt < 2; mt++)
            #pragma unroll
            for (int ks = 0; ks < 4; ks++)
                MMA16816(lacc[mt], aP[mt][ks], ONES, ONES);

        // ---- O += P @ V; V frags shared by both m-tiles
        #pragma unroll
        for (int ks = 0; ks < 4; ks++) {
            uint32_t kso = vslot + (uint32_t)(ks * 2048);
            #pragma unroll
            for (int dp = 0; dp < 4; dp++) {
                uint32_t vf[4];
                LDSM4T(vf, kso + a0[dp]);
                #pragma unroll
                for (int mt = 0; mt < 2; mt++) {
                    MMA16816(oacc[mt][2*dp],     aP[mt][ks], vf[0], vf[1]);
                    MMA16816(oacc[mt][2*dp + 1], aP[mt][ks], vf[2], vf[3]);
                }
            }
        }

        if (c + 2 < 16) issue(c + 2);
    }

    #pragma unroll
    for (int mt = 0; mt < 2; mt++) {
        float il1 = __frcp_rn(lacc[mt][0]), il2 = __frcp_rn(lacc[mt][2]);
        int seq1 = qb + w * 32 + mt * 16 + (lane >> 2);
        int seq2 = seq1 + 8;
        size_t base1 = ((size_t)(b * Nn + seq1)) * Dd + h * DHh;
        size_t base2 = ((size_t)(b * Nn + seq2)) * Dd + h * DHh;
        #pragma unroll
        for (int nt = 0; nt < 8; nt++) {
            int col = nt * 8 + (lane & 3) * 2;
            *(uint32_t*)(g_bO + base1 + col) = packbf(oacc[mt][nt][1] * il1, oacc[mt][nt][0] * il1);
            *(uint32_t*)(g_bO + base2 + col) = packbf(oacc[mt][nt][3] * il2, oacc[mt][nt][2] * il2);
        }
    }
}

// ============================================================
// Epilogue: warp-per-row, shuffle-only reductions. grid = Mrows/8.
// ============================================================
__device__ __forceinline__ float warp_sum(float v)
{
    #pragma unroll
    for (int off = 16; off > 0; off >>= 1)
        v += __shfl_xor_sync(0xffffffffu, v, off);
    return v;
}

__global__ __launch_bounds__(256) void epilogue_kernel(
        const float* __restrict__ q,
        const float* __restrict__ g1, const float* __restrict__ b1,
        const float* __restrict__ g2, const float* __restrict__ b2,
        float* __restrict__ out)
{
    int w = threadIdx.x >> 5, lane = threadIdx.x & 31;
    int row = blockIdx.x * 8 + w;
    const float4* m4 = (const float4*)(g_mha + (size_t)row * Dd);
    const float4* q4 = (const float4*)(q + (size_t)row * Dd);

    float4 x[8];
    float s = 0.f;
    #pragma unroll
    for (int i = 0; i < 8; i++) {
        int idx = i * 32 + lane;
        float4 a = m4[idx], b = q4[idx];
        x[i].x = a.x + b.x; x[i].y = a.y + b.y;
        x[i].z = a.z + b.z; x[i].w = a.w + b.w;
        s += x[i].x + x[i].y + x[i].z + x[i].w;
    }
    float mu = warp_sum(s) * (1.f / 1024.f);

    float vs = 0.f;
    #pragma unroll
    for (int i = 0; i < 8; i++) {
        float dx = x[i].x - mu, dy = x[i].y - mu, dz = x[i].z - mu, dw = x[i].w - mu;
        vs += dx*dx + dy*dy + dz*dz + dw*dw;
    }
    float rs = rsqrtf(warp_sum(vs) * (1.f / 1024.f) + 1e-5f);

    float s2 = 0.f;
    #pragma unroll
    for (int i = 0; i < 8; i++) {
        int idx = i * 32 + lane;
        float4 g = ((const float4*)g1)[idx];
        float4 bb = ((const float4*)b1)[idx];
        float r0 = (x[i].x - mu) * rs * g.x + bb.x;
        float r1 = (x[i].y - mu) * rs * g.y + bb.y;
        float r2 = (x[i].z - mu) * rs * g.z + bb.z;
        float r3 = (x[i].w - mu) * rs * g.w + bb.w;
        x[i].x = (r0 > 0.f) ? (r0 + r0) : r0;
        x[i].y = (r1 > 0.f) ? (r1 + r1) : r1;
        x[i].z = (r2 > 0.f) ? (r2 + r2) : r2;
        x[i].w = (r3 > 0.f) ? (r3 + r3) : r3;
        s2 += x[i].x + x[i].y + x[i].z + x[i].w;
    }
    float mu2 = warp_sum(s2) * (1.f / 1024.f);

    float vs2 = 0.f;
    #pragma unroll
    for (int i = 0; i < 8; i++) {
        float dx = x[i].x - mu2, dy = x[i].y - mu2, dz = x[i].z - mu2, dw = x[i].w - mu2;
        vs2 += dx*dx + dy*dy + dz*dz + dw*dw;
    }
    float rs2 = rsqrtf(warp_sum(vs2) * (1.f / 1024.f) + 1e-5f);

    float4* o4 = (float4*)(out + (size_t)row * Dd);
    #pragma unroll
    for (int i = 0; i < 8; i++) {
        int idx = i * 32 + lane;
        float4 g = ((const float4*)g2)[idx];
        float4 bb = ((const float4*)b2)[idx];
        float4 ov;
        ov.x = (x[i].x - mu2) * rs2 * g.x + bb.x;
        ov.y = (x[i].y - mu2) * rs2 * g.y + bb.y;
        ov.z = (x[i].z - mu2) * rs2 * g.z + bb.z;
        ov.w = (x[i].w - mu2) * rs2 * g.w + bb.w;
        o4[idx] = ov;
    }
}

// ============================================================
extern "C" void kernel_launch(void* const* d_in, const int* in_sizes, int n_in,
                              void* d_out, int out_size)
{
    const float* k  = (const float*)d_in[0];
    const float* q  = (const float*)d_in[1];
    const float* r  = (const float*)d_in[2];
    const float* Wk = (const float*)d_in[3];
    const float* bk = (const float*)d_in[4];
    const float* Wq = (const float*)d_in[5];
    const float* bq = (const float*)d_in[6];
    const float* Wv = (const float*)d_in[7];
    const float* bv = (const float*)d_in[8];
    const float* Wo = (const float*)d_in[9];
    const float* bo = (const float*)d_in[10];
    const float* g1 = (const float*)d_in[11];
    const float* b1 = (const float*)d_in[12];
    const float* g2 = (const float*)d_in[13];
    const float* b2 = (const float*)d_in[14];
    float* out = (float*)d_out;

    static int attrs_set = 0;
    if (!attrs_set) {
        cudaFuncSetAttribute(gemm_qkv, cudaFuncAttributeMaxDynamicSharedMemorySize, GEMM_SMEM);
        cudaFuncSetAttribute(gemm_o,   cudaFuncAttributeMaxDynamicSharedMemorySize, GEMM_SMEM);
        cudaFuncSetAttribute(attn_mma, cudaFuncAttributeMaxDynamicSharedMemorySize, ATTN_SMEM);
        attrs_set = 1;
    }

    convert_w4<<<dim3(256, 4), 256>>>(Wk, Wq, Wv, Wo);
    convert_x3<<<dim3(2048, 3), 256>>>(k, q, r);

    gemm_qkv<<<dim3(8, 64, 3), 128, GEMM_SMEM>>>(bk, bq, bv);

    dim3 ga(Nn / 128, Bb * Hh);
    attn_mma<<<ga, 128, ATTN_SMEM>>>();

    gemm_o<<<dim3(8, 64), 128, GEMM_SMEM>>>(bo);

    epilogue_kernel<<<Mrows / 8, 256>>>(q, g1, b1, g2, b2, out);
}

// round 17
// speedup vs baseline: 1.4085x; 1.4085x over previous
#include <cuda_runtime.h>
#include <cuda_bf16.h>
#include <math.h>
#include <stdint.h>

#define Bb 8
#define Nn 1024
#define Dd 1024
#define Hh 16
#define DHh 64
#define Mrows (Bb*Nn)

// 0.125 (1/sqrt(DH)) * log2(e): folds attn scale + base-2 softmax into Q
#define SCQ 0.18033688011112042f

// ---- scratch (static device globals; no allocations allowed) ----
__device__ __nv_bfloat16 g_mhb[Mrows*Dd];         // o @ Wo^T + bo (bf16)
__device__ __nv_bfloat16 g_sX3[3ull*Mrows*Dd];    // converted k,q,r
__device__ __nv_bfloat16 g_sW4[4ull*Dd*Dd];       // converted Wk,Wq,Wv,Wo
__device__ __nv_bfloat16 g_bQ[Bb*Hh*Nn*DHh];      // [b,h,n,dh] (pre-scaled by SCQ)
__device__ __nv_bfloat16 g_bK[Bb*Hh*Nn*DHh];
__device__ __nv_bfloat16 g_bV[Bb*Hh*Nn*DHh];
__device__ __nv_bfloat16 g_bO[Mrows*Dd];          // attention out, [B*N, D] flat bf16

// ============================================================
// helpers
// ============================================================
__device__ __forceinline__ uint32_t smem_u32(const void* p) {
    return (uint32_t)__cvta_generic_to_shared(p);
}

#define CPA(dst, src) asm volatile("cp.async.cg.shared.global [%0], [%1], 16;" :: "r"(dst), "l"(src))
#define CPC()  asm volatile("cp.async.commit_group;" ::: "memory")
#define CPW1() asm volatile("cp.async.wait_group 1;" ::: "memory")
#define CPW0() asm volatile("cp.async.wait_group 0;" ::: "memory")

#define LDSM4(r, a) \
    asm volatile("ldmatrix.sync.aligned.m8n8.x4.shared.b16 {%0,%1,%2,%3}, [%4];" \
        : "=r"((r)[0]), "=r"((r)[1]), "=r"((r)[2]), "=r"((r)[3]) : "r"(a))

#define LDSM4T(r, a) \
    asm volatile("ldmatrix.sync.aligned.m8n8.x4.trans.shared.b16 {%0,%1,%2,%3}, [%4];" \
        : "=r"((r)[0]), "=r"((r)[1]), "=r"((r)[2]), "=r"((r)[3]) : "r"(a))

#define MMA16816(c, a, b0, b1) \
    asm volatile("mma.sync.aligned.m16n8k16.row.col.f32.bf16.bf16.f32 " \
        "{%0,%1,%2,%3},{%4,%5,%6,%7},{%8,%9},{%0,%1,%2,%3};" \
        : "+f"((c)[0]), "+f"((c)[1]), "+f"((c)[2]), "+f"((c)[3]) \
        : "r"((a)[0]), "r"((a)[1]), "r"((a)[2]), "r"((a)[3]), "r"(b0), "r"(b1))

// d = a*b + 0 (separate zero C operand: no accumulator pre-init needed)
#define MMA16816Z(c, a, b0, b1) \
    asm volatile("mma.sync.aligned.m16n8k16.row.col.f32.bf16.bf16.f32 " \
        "{%0,%1,%2,%3},{%4,%5,%6,%7},{%8,%9},{%10,%10,%10,%10};" \
        : "=f"((c)[0]), "=f"((c)[1]), "=f"((c)[2]), "=f"((c)[3]) \
        : "r"((a)[0]), "r"((a)[1]), "r"((a)[2]), "r"((a)[3]), "r"(b0), "r"(b1), "f"(0.f))

__device__ __forceinline__ uint32_t packbf(float hi, float lo) {
    uint32_t d;
    asm("cvt.rn.bf16x2.f32 %0, %1, %2;" : "=r"(d) : "f"(hi), "f"(lo));
    return d;
}

// fast 2^x, |x| bounded, cubic (P feeds bf16; poly err << bf16 rounding)
__device__ __forceinline__ float exp2q(float x) {
    float z = x + 12582912.0f;
    int   xi = __float_as_int(z) - 0x4B400000;
    float f = x - (z - 12582912.0f);
    float p = fmaf(f, 0.0790211f, 0.2243367f);
    p = fmaf(f, p, 0.6958793f);
    p = fmaf(f, p, 1.0f);
    return __int_as_float(__float_as_int(p) + (xi << 23));
}

// swizzled smem byte offset: 128B-row arrays, u = 16B-unit index 0..7
__device__ __forceinline__ uint32_t offA(uint32_t r, uint32_t u) {
    return r * 128u + ((u ^ (r & 7u)) << 4);
}

// ============================================================
// fused fp32 -> bf16 converters (4 float4 per thread)
// ============================================================
__global__ __launch_bounds__(256) void convert_x3(const float* __restrict__ k,
                                                  const float* __restrict__ q,
                                                  const float* __restrict__ r)
{
    int which = blockIdx.y;
    const float* src = (which == 0) ? k : (which == 1) ? q : r;
    __nv_bfloat16* dst = g_sX3 + (size_t)which * (Mrows * Dd);
    int base = blockIdx.x * 1024 + threadIdx.x;
    #pragma unroll
    for (int u = 0; u < 4; u++) {
        int i = base + u * 256;
        float4 v = ((const float4*)src)[i];
        uint2 pk;
        pk.x = packbf(v.y, v.x);
        pk.y = packbf(v.w, v.z);
        ((uint2*)dst)[i] = pk;
    }
}

__global__ __launch_bounds__(256) void convert_w4(const float* __restrict__ w0,
                                                  const float* __restrict__ w1,
                                                  const float* __restrict__ w2,
                                                  const float* __restrict__ w3)
{
    int which = blockIdx.y;
    const float* src = (which == 0) ? w0 : (which == 1) ? w1
                     : (which == 2) ? w2 : w3;
    __nv_bfloat16* dst = g_sW4 + (size_t)which * (Dd * Dd);
    int base = blockIdx.x * 1024 + threadIdx.x;
    #pragma unroll
    for (int u = 0; u < 4; u++) {
        int i = base + u * 256;
        float4 v = ((const float4*)src)[i];
        uint2 pk;
        pk.x = packbf(v.y, v.x);
        pk.y = packbf(v.w, v.z);
        ((uint2*)dst)[i] = pk;
    }
}

// ============================================================
// bf16 mma GEMM core: out = X @ W^T + bias
// CTA 128x128, 8 warps (2x4), warp tile 64x32, K-chunk 64,
// 3-stage cp.async ring (96KB), ONE barrier/iter, 16 iters, 2 CTAs/SM.
// 128B-row tiles with offA swizzle; K-half2 addresses = half1 ^ 64.
// ============================================================
#define GARR 16384                       // one 128x128B array
#define GSTAGE (2*GARR)                  // A + B = 32KB
#define GEMM_SMEM (3*GSTAGE)             // 96KB

__device__ __forceinline__ void gemm_core(const __nv_bfloat16* __restrict__ A,
                                          const __nv_bfloat16* __restrict__ W,
                                          const float* __restrict__ bias,
                                          int out_sel, char* smem)
{
    uint32_t sb = smem_u32(smem);

    int t = threadIdx.x;
    int wid = t >> 5, lane = t & 31;
    int wm = wid >> 2, wn = wid & 3;
    int m0 = blockIdx.y * 128, n0 = blockIdx.x * 128;

    // copy: thread t -> row cr, 4 contiguous 16B units starting at cu4
    int cr = t >> 1;
    int cu4 = (t & 1) * 4;
    const char* pA = (const char*)(A + (size_t)(m0 + cr) * 1024 + cu4 * 8);
    const char* pB = (const char*)(W + (size_t)(n0 + cr) * 1024 + cu4 * 8);
    uint32_t dd[4];
    #pragma unroll
    for (int j = 0; j < 4; j++)
        dd[j] = offA((uint32_t)cr, (uint32_t)(cu4 + j));

    auto issue = [&](int it) {
        uint32_t st = sb + (uint32_t)(it % 3) * GSTAGE;
        size_t kb = (size_t)it * 128;            // 64 bf16 per chunk
        #pragma unroll
        for (int j = 0; j < 4; j++) {
            CPA(st + dd[j], pA + kb + j * 16);
            CPA(st + GARR + dd[j], pB + kb + j * 16);
        }
        CPC();
    };

    float acc[4][4][4];
    #pragma unroll
    for (int i = 0; i < 4; i++)
        #pragma unroll
        for (int j = 0; j < 4; j++)
            #pragma unroll
            for (int u = 0; u < 4; u++) acc[i][j][u] = 0.f;

    // A fragment per-lane offsets: a0[ks] (ks=0..3 covers K0..63)
    uint32_t a0[4];
    #pragma unroll
    for (int i = 0; i < 4; i++)
        a0[i] = (uint32_t)(lane & 15) * 128u
              + ((((uint32_t)i * 2u + (uint32_t)(lane >> 4)) ^ (uint32_t)(lane & 7)) << 4);
    // B fragment offsets (K0..31); K32..63 = ^64
    uint32_t bAddr[4];
    #pragma unroll
    for (int nt = 0; nt < 4; nt++)
        bAddr[nt] = offA((uint32_t)(wn*32 + nt*8 + (lane & 7)), (uint32_t)(lane >> 3));

    uint32_t mtoff[4];
    #pragma unroll
    for (int mt = 0; mt < 4; mt++)
        mtoff[mt] = (uint32_t)((wm*64 + mt*16) * 128);

    issue(0); issue(1);

    for (int it = 0; it < 16; it++) {
        if (it < 15) CPW1(); else CPW0();
        __syncthreads();

        uint32_t st = sb + (uint32_t)(it % 3) * GSTAGE;

        #pragma unroll
        for (int half = 0; half < 2; half++) {
            uint32_t hx = (uint32_t)(half << 6);     // ^64 for K-half 2
            uint32_t ah[4][2][4];
            #pragma unroll
            for (int mt = 0; mt < 4; mt++)
                #pragma unroll
                for (int kk = 0; kk < 2; kk++)
                    LDSM4(ah[mt][kk], (st + mtoff[mt] + a0[half*2 + kk]));
            #pragma unroll
            for (int nt = 0; nt < 4; nt++) {
                uint32_t bf[4];
                LDSM4(bf, (st + GARR + bAddr[nt]) ^ hx);
                #pragma unroll
                for (int mt = 0; mt < 4; mt++)
                    #pragma unroll
                    for (int kk = 0; kk < 2; kk++)
                        MMA16816(acc[mt][nt], ah[mt][kk], bf[kk*2], bf[kk*2+1]);
            }
        }

        if (it + 2 < 16) issue(it + 2);   // writes slot (it-1)%3: safe post-barrier
    }

    // ---- epilogue
    float sc = (out_sel == 1) ? SCQ : 1.0f;
    #pragma unroll
    for (int mt = 0; mt < 4; mt++) {
        #pragma unroll
        for (int nt = 0; nt < 4; nt++) {
            int row = m0 + wm*64 + mt*16 + (lane >> 2);
            int col = n0 + wn*32 + nt*8 + (lane & 3)*2;
            float b0v = bias[col], b1v = bias[col + 1];
            float v0 = (acc[mt][nt][0] + b0v) * sc;
            float v1 = (acc[mt][nt][1] + b1v) * sc;
            float v2 = (acc[mt][nt][2] + b0v) * sc;
            float v3 = (acc[mt][nt][3] + b1v) * sc;
            if (out_sel < 3) {
                __nv_bfloat16* out = (out_sel == 0) ? g_bK : (out_sel == 1) ? g_bQ : g_bV;
                int bidx = row >> 10;
                int iseq = row & 1023;
                int h = col >> 6;
                int dd2 = col & 63;
                size_t base = (((size_t)(bidx*Hh + h) * Nn) + iseq) * DHh + dd2;
                *(uint32_t*)(out + base)           = packbf(v1, v0);
                *(uint32_t*)(out + base + 8*DHh)   = packbf(v3, v2);
            } else {
                *(uint32_t*)(g_mhb + (size_t)row * Dd + col)       = packbf(v1, v0);
                *(uint32_t*)(g_mhb + (size_t)(row + 8) * Dd + col) = packbf(v3, v2);
            }
        }
    }
}

__global__ __launch_bounds__(256, 2) void gemm_qkv(const float* __restrict__ bk,
                                                   const float* __restrict__ bq,
                                                   const float* __restrict__ bv)
{
    extern __shared__ __align__(16) char smem[];
    int z = blockIdx.z;
    const float* bias = (z == 0) ? bk : (z == 1) ? bq : bv;
    gemm_core(g_sX3 + (size_t)z * (Mrows * Dd),
              g_sW4 + (size_t)z * (Dd * Dd),
              bias, z, smem);
}

__global__ __launch_bounds__(256, 2) void gemm_o(const float* __restrict__ bo)
{
    extern __shared__ __align__(16) char smem[];
    gemm_core(g_bO, g_sW4 + 3ull * (Dd * Dd), bo, 3, smem);
}

// ============================================================
// Flash attention: one-pass softmax, row sums via ones-MMA,
// hoisted swizzled LDSM addresses, cubic exp2, zero-C first MMA.
// 8 warps x 16 Q-rows, 2 CTAs/SM.
// ============================================================
#define AQ_BYTES 16384
#define AKV_BYTES 8192
#define ATTN_SMEM (AQ_BYTES + 6*AKV_BYTES)   // 64KB

__global__ __launch_bounds__(256, 2) void attn_mma()
{
    extern __shared__ __align__(16) char dsm[];
    uint32_t sQ = smem_u32(dsm);
    uint32_t sKb = sQ + AQ_BYTES;
    uint32_t sVb = sKb + 3 * AKV_BYTES;

    int t = threadIdx.x;
    int w = t >> 5, lane = t & 31;
    int bh = blockIdx.y;
    int qb = blockIdx.x * 128;
    int b = bh >> 4, h = bh & 15;

    const __nv_bfloat16* Qg = g_bQ + ((size_t)bh * Nn + qb) * DHh;
    const __nv_bfloat16* Kg = g_bK + (size_t)bh * Nn * DHh;
    const __nv_bfloat16* Vg = g_bV + (size_t)bh * Nn * DHh;

    #pragma unroll
    for (int i = 0; i < 4; i++) {
        int idx = t + i * 256;
        int r = idx >> 3, u = idx & 7;
        uint4 v = *(const uint4*)(Qg + r * DHh + u * 8);
        *(uint4*)(dsm + offA((uint32_t)r, (uint32_t)u)) = v;
    }

    uint32_t a0[4];
    #pragma unroll
    for (int i = 0; i < 4; i++)
        a0[i] = (uint32_t)(lane & 15) * 128u
              + ((((uint32_t)i * 2u + (uint32_t)(lane >> 4)) ^ (uint32_t)(lane & 7)) << 4);

    int cr = t >> 2;
    int cu = (t & 3) * 2;
    auto issue = [&](int c) {
        int st = c % 3;
        const __nv_bfloat16* ks = Kg + (size_t)(c * 64 + cr) * DHh;
        const __nv_bfloat16* vs = Vg + (size_t)(c * 64 + cr) * DHh;
        uint32_t o0 = offA((uint32_t)cr, (uint32_t)cu);
        uint32_t o1 = offA((uint32_t)cr, (uint32_t)(cu + 1));
        uint32_t kslot = sKb + (uint32_t)st * AKV_BYTES;
        uint32_t vslot = sVb + (uint32_t)st * AKV_BYTES;
        CPA(kslot + o0, ks + cu * 8);
        CPA(kslot + o1, ks + cu * 8 + 8);
        CPA(vslot + o0, vs + cu * 8);
        CPA(vslot + o1, vs + cu * 8 + 8);
        CPC();
    };

    issue(0); issue(1);
    __syncthreads();

    uint32_t aQ[4][4];
    #pragma unroll
    for (int ks = 0; ks < 4; ks++)
        LDSM4(aQ[ks], sQ + (uint32_t)(w * 2048) + a0[ks]);

    float oacc[8][4];
    #pragma unroll
    for (int nt = 0; nt < 8; nt++)
        #pragma unroll
        for (int u = 0; u < 4; u++) oacc[nt][u] = 0.f;
    float lacc[4] = {0.f, 0.f, 0.f, 0.f};
    const uint32_t ONES = 0x3F803F80u;

    for (int c = 0; c < 16; c++) {
        if (c < 15) CPW1(); else CPW0();
        __syncthreads();
        int st = c % 3;
        uint32_t kslot = sKb + (uint32_t)st * AKV_BYTES;
        uint32_t vslot = sVb + (uint32_t)st * AKV_BYTES;

        // ---- S = Q @ K^T (16 x 64 per warp); first k-step writes (zero-C)
        float s[8][4];
        #pragma unroll
        for (int sg = 0; sg < 4; sg++) {
            uint32_t sgo = kslot + (uint32_t)(sg * 2048);
            uint32_t kf[4][4];
            #pragma unroll
            for (int ks = 0; ks < 4; ks++)
                LDSM4(kf[ks], sgo + a0[ks]);
            MMA16816Z(s[2*sg],     aQ[0], kf[0][0], kf[0][2]);
            MMA16816Z(s[2*sg + 1], aQ[0], kf[0][1], kf[0][3]);
            #pragma unroll
            for (int ks = 1; ks < 4; ks++) {
                MMA16816(s[2*sg],     aQ[ks], kf[ks][0], kf[ks][2]);
                MMA16816(s[2*sg + 1], aQ[ks], kf[ks][1], kf[ks][3]);
            }
        }

        uint32_t aP[4][4];
        #pragma unroll
        for (int nt = 0; nt < 8; nt++) {
            s[nt][0] = exp2q(s[nt][0]);
            s[nt][1] = exp2q(s[nt][1]);
            s[nt][2] = exp2q(s[nt][2]);
            s[nt][3] = exp2q(s[nt][3]);
        }
        #pragma unroll
        for (int ks = 0; ks < 4; ks++) {
            aP[ks][0] = packbf(s[2*ks][1],     s[2*ks][0]);
            aP[ks][1] = packbf(s[2*ks][3],     s[2*ks][2]);
            aP[ks][2] = packbf(s[2*ks+1][1],   s[2*ks+1][0]);
            aP[ks][3] = packbf(s[2*ks+1][3],   s[2*ks+1][2]);
        }

        #pragma unroll
        for (int ks = 0; ks < 4; ks++)
            MMA16816(lacc, aP[ks], ONES, ONES);

        #pragma unroll
        for (int ks = 0; ks < 4; ks++) {
            uint32_t kso = vslot + (uint32_t)(ks * 2048);
            #pragma unroll
            for (int dp = 0; dp < 4; dp++) {
                uint32_t vf[4];
                LDSM4T(vf, kso + a0[dp]);
                MMA16816(oacc[2*dp],     aP[ks], vf[0], vf[1]);
                MMA16816(oacc[2*dp + 1], aP[ks], vf[2], vf[3]);
            }
        }

        if (c + 2 < 16) issue(c + 2);
    }

    float il1 = __frcp_rn(lacc[0]), il2 = __frcp_rn(lacc[2]);
    int seq1 = qb + w * 16 + (lane >> 2);
    int seq2 = seq1 + 8;
    size_t base1 = ((size_t)(b * Nn + seq1)) * Dd + h * DHh;
    size_t base2 = ((size_t)(b * Nn + seq2)) * Dd + h * DHh;
    #pragma unroll
    for (int nt = 0; nt < 8; nt++) {
        int col = nt * 8 + (lane & 3) * 2;
        *(uint32_t*)(g_bO + base1 + col) = packbf(oacc[nt][1] * il1, oacc[nt][0] * il1);
        *(uint32_t*)(g_bO + base2 + col) = packbf(oacc[nt][3] * il2, oacc[nt][2] * il2);
    }
}

// ============================================================
// Epilogue: warp-per-row, shuffle-only reductions, bf16 mha input.
// grid = Mrows/8.  residual = LN(mha + q); out = LN(relu(res)+res)
// ============================================================
__device__ __forceinline__ float warp_sum(float v)
{
    #pragma unroll
    for (int off = 16; off > 0; off >>= 1)
        v += __shfl_xor_sync(0xffffffffu, v, off);
    return v;
}

__global__ __launch_bounds__(256) void epilogue_kernel(
        const float* __restrict__ q,
        const float* __restrict__ g1, const float* __restrict__ b1,
        const float* __restrict__ g2, const float* __restrict__ b2,
        float* __restrict__ out)
{
    int w = threadIdx.x >> 5, lane = threadIdx.x & 31;
    int row = blockIdx.x * 8 + w;
    const uint2* m2 = (const uint2*)(g_mhb + (size_t)row * Dd);   // 4 bf16 per uint2
    const float4* q4 = (const float4*)(q + (size_t)row * Dd);

    float4 x[8];
    float s = 0.f;
    #pragma unroll
    for (int i = 0; i < 8; i++) {
        int idx = i * 32 + lane;
        uint2 mv = m2[idx];
        float2 f01 = __bfloat1622float2(*reinterpret_cast<__nv_bfloat162*>(&mv.x));
        float2 f23 = __bfloat1622float2(*reinterpret_cast<__nv_bfloat162*>(&mv.y));
        float4 b = q4[idx];
        x[i].x = f01.x + b.x; x[i].y = f01.y + b.y;
        x[i].z = f23.x + b.z; x[i].w = f23.y + b.w;
        s += x[i].x + x[i].y + x[i].z + x[i].w;
    }
    float mu = warp_sum(s) * (1.f / 1024.f);

    float vs = 0.f;
    #pragma unroll
    for (int i = 0; i < 8; i++) {
        float dx = x[i].x - mu, dy = x[i].y - mu, dz = x[i].z - mu, dw = x[i].w - mu;
        vs += dx*dx + dy*dy + dz*dz + dw*dw;
    }
    float rs = rsqrtf(warp_sum(vs) * (1.f / 1024.f) + 1e-5f);

    float s2 = 0.f;
    #pragma unroll
    for (int i = 0; i < 8; i++) {
        int idx = i * 32 + lane;
        float4 g = ((const float4*)g1)[idx];
        float4 bb = ((const float4*)b1)[idx];
        float r0 = (x[i].x - mu) * rs * g.x + bb.x;
        float r1 = (x[i].y - mu) * rs * g.y + bb.y;
        float r2 = (x[i].z - mu) * rs * g.z + bb.z;
        float r3 = (x[i].w - mu) * rs * g.w + bb.w;
        x[i].x = (r0 > 0.f) ? (r0 + r0) : r0;
        x[i].y = (r1 > 0.f) ? (r1 + r1) : r1;
        x[i].z = (r2 > 0.f) ? (r2 + r2) : r2;
        x[i].w = (r3 > 0.f) ? (r3 + r3) : r3;
        s2 += x[i].x + x[i].y + x[i].z + x[i].w;
    }
    float mu2 = warp_sum(s2) * (1.f / 1024.f);

    float vs2 = 0.f;
    #pragma unroll
    for (int i = 0; i < 8; i++) {
        float dx = x[i].x - mu2, dy = x[i].y - mu2, dz = x[i].z - mu2, dw = x[i].w - mu2;
        vs2 += dx*dx + dy*dy + dz*dz + dw*dw;
    }
    float rs2 = rsqrtf(warp_sum(vs2) * (1.f / 1024.f) + 1e-5f);

    float4* o4 = (float4*)(out + (size_t)row * Dd);
    #pragma unroll
    for (int i = 0; i < 8; i++) {
        int idx = i * 32 + lane;
        float4 g = ((const float4*)g2)[idx];
        float4 bb = ((const float4*)b2)[idx];
        float4 ov;
        ov.x = (x[i].x - mu2) * rs2 * g.x + bb.x;
        ov.y = (x[i].y - mu2) * rs2 * g.y + bb.y;
        ov.z = (x[i].z - mu2) * rs2 * g.z + bb.z;
        ov.w = (x[i].w - mu2) * rs2 * g.w + bb.w;
        o4[idx] = ov;
    }
}

// ============================================================
extern "C" void kernel_launch(void* const* d_in, const int* in_sizes, int n_in,
                              void* d_out, int out_size)
{
    const float* k  = (const float*)d_in[0];
    const float* q  = (const float*)d_in[1];
    const float* r  = (const float*)d_in[2];
    const float* Wk = (const float*)d_in[3];
    const float* bk = (const float*)d_in[4];
    const float* Wq = (const float*)d_in[5];
    const float* bq = (const float*)d_in[6];
    const float* Wv = (const float*)d_in[7];
    const float* bv = (const float*)d_in[8];
    const float* Wo = (const float*)d_in[9];
    const float* bo = (const float*)d_in[10];
    const float* g1 = (const float*)d_in[11];
    const float* b1 = (const float*)d_in[12];
    const float* g2 = (const float*)d_in[13];
    const float* b2 = (const float*)d_in[14];
    float* out = (float*)d_out;

    static int attrs_set = 0;
    if (!attrs_set) {
        cudaFuncSetAttribute(gemm_qkv, cudaFuncAttributeMaxDynamicSharedMemorySize, GEMM_SMEM);
        cudaFuncSetAttribute(gemm_o,   cudaFuncAttributeMaxDynamicSharedMemorySize, GEMM_SMEM);
        cudaFuncSetAttribute(attn_mma, cudaFuncAttributeMaxDynamicSharedMemorySize, ATTN_SMEM);
        attrs_set = 1;
    }

    dim3 blk(256);

    convert_w4<<<dim3(256, 4), blk>>>(Wk, Wq, Wv, Wo);
    convert_x3<<<dim3(2048, 3), blk>>>(k, q, r);

    gemm_qkv<<<dim3(8, 64, 3), blk, GEMM_SMEM>>>(bk, bq, bv);

    dim3 ga(Nn / 128, Bb * Hh);
    attn_mma<<<ga, blk, ATTN_SMEM>>>();

    gemm_o<<<dim3(8, 64), blk, GEMM_SMEM>>>(bo);

    epilogue_kernel<<<Mrows / 8, blk>>>(q, g1, b1, g2, b2, out);
}